// round 6
// baseline (speedup 1.0000x reference)
#include <cuda_runtime.h>
#include <cstdint>

// Problem constants
#define N_  16
#define T_  4096
#define I_  256
#define H_  512
#define C_  128     // number of chunks
#define L_  32      // chunk length, C_*L_ == T_

// -------- static device scratch (no allocation allowed) --------
__device__ float g_Wt [H_*H_];   // S = Whh^T row-major: Wt[k*H+j] = Whh[j*H+k]
__device__ float g_Wit[I_*H_];   // Wi^T : Wit[i*H+j] = Wi[j*I+i]
__device__ float g_P0 [H_*H_];   // squaring ping  (S^2k row-major)
__device__ float g_P1 [H_*H_];   // squaring pong
__device__ float g_lend[C_*N_*H_]; // local state at each chunk end
__device__ float g_hb  [C_*N_*H_]; // true hidden at each chunk end

// monotonic grid barrier state (never reset -> deterministic across graph replays)
__device__ unsigned g_cnt = 0;
__device__ unsigned g_rel = 0;

__device__ __forceinline__ void grid_barrier_dev(unsigned total)
{
    __syncthreads();
    if (threadIdx.x == 0) {
        __threadfence();
        unsigned my = atomicAdd(&g_cnt, 1u);
        if ((my % total) == total - 1u) {
            atomicAdd(&g_rel, 1u);
        } else {
            unsigned need = my / total + 1u;
            while (*((volatile unsigned*)&g_rel) < need) { }
        }
    }
    __syncthreads();
}

// -------- K0: build Wt (S row-major) and Wit (Wi transpose) --------
__global__ void k_prep(const float* __restrict__ Whh, const float* __restrict__ Wi)
{
    int idx = blockIdx.x * blockDim.x + threadIdx.x;   // over H*H
    if (idx < H_*H_) {
        int j = idx / H_, k = idx % H_;
        g_Wt[k*H_ + j] = Whh[idx];
    }
    if (idx < H_*I_) {
        int j = idx / I_, i = idx % I_;
        g_Wit[i*H_ + j] = Wi[idx];
    }
}

// ---------------------------------------------------------------------------
// gemm_k: C = A[M,K] @ B[K,Nn]   (both row-major, C pitch = Nn)
// tile 128m x 64n, BK=16, 256 threads, per-thread 8m x 4n scalar FFMA.
// MODE 0: plain store (matrix squaring)
// MODE 1: RNN projection epilogue (q shift + bias + initial)
// ---------------------------------------------------------------------------
template<int MODE>
__global__ void __launch_bounds__(256, 2)
gemm_k(const float* __restrict__ A, const float* __restrict__ B,
       float* __restrict__ Cc, int M, int K, int Nn,
       const float* __restrict__ bias, const float* __restrict__ initial)
{
    __shared__ __align__(16) float As[16][136];  // [k][m]
    __shared__ __align__(16) float Bs[16][64];   // [k][n]

    const int tid = threadIdx.x;
    const int bm = blockIdx.y * 128;
    const int bn = blockIdx.x * 64;
    const int tx = tid & 15;        // n group: bn + tx*4
    const int ty = tid >> 4;        // m group: bm + ty*8

    const int arow = tid >> 1;
    const int akof = (tid & 1) * 8;
    const int brow = tid >> 4;
    const int bcol = (tid & 15) * 4;

    float acc[8][4];
#pragma unroll
    for (int i = 0; i < 8; ++i)
#pragma unroll
        for (int jj = 0; jj < 4; ++jj) acc[i][jj] = 0.f;

    for (int kt = 0; kt < K; kt += 16) {
        const float* Ab = A + (size_t)(bm + arow) * K + kt + akof;
        float4 a0 = *(const float4*)&Ab[0];
        float4 a1 = *(const float4*)&Ab[4];
        As[akof+0][arow] = a0.x; As[akof+1][arow] = a0.y;
        As[akof+2][arow] = a0.z; As[akof+3][arow] = a0.w;
        As[akof+4][arow] = a1.x; As[akof+5][arow] = a1.y;
        As[akof+6][arow] = a1.z; As[akof+7][arow] = a1.w;
        *(float4*)&Bs[brow][bcol] = *(const float4*)&B[(size_t)(kt + brow) * Nn + bn + bcol];
        __syncthreads();

#pragma unroll
        for (int k = 0; k < 16; ++k) {
            float4 av0 = *(const float4*)&As[k][ty*8];
            float4 av1 = *(const float4*)&As[k][ty*8 + 4];
            float4 bv  = *(const float4*)&Bs[k][tx*4];
            float am[8] = {av0.x,av0.y,av0.z,av0.w, av1.x,av1.y,av1.z,av1.w};
            float bb[4] = {bv.x,bv.y,bv.z,bv.w};
#pragma unroll
            for (int i = 0; i < 8; ++i)
#pragma unroll
                for (int jj = 0; jj < 4; ++jj)
                    acc[i][jj] = fmaf(am[i], bb[jj], acc[i][jj]);
        }
        __syncthreads();
    }

    if (MODE == 0) {
#pragma unroll
        for (int i = 0; i < 8; ++i) {
            int m = bm + ty*8 + i;
            *(float4*)&Cc[(size_t)m * Nn + bn + tx*4]
                = make_float4(acc[i][0], acc[i][1], acc[i][2], acc[i][3]);
        }
    } else {
        float4 bv = *(const float4*)&bias[bn + tx*4];
#pragma unroll
        for (int i = 0; i < 8; ++i) {
            int r = bm + ty*8 + i;
            int s = r & (T_ - 1);
            int n = r >> 12;
            float4 v = make_float4(acc[i][0]+bv.x, acc[i][1]+bv.y,
                                   acc[i][2]+bv.z, acc[i][3]+bv.w);
            if (s < T_ - 1)
                *(float4*)&Cc[((size_t)n*T_ + s + 1)*H_ + bn + tx*4] = v;
            if (s == 0) {
                float4 iv = *(const float4*)&initial[(size_t)n*H_ + bn + tx*4];
                *(float4*)&Cc[((size_t)n*T_)*H_ + bn + tx*4]
                    = make_float4(v.x+iv.x, v.y+iv.y, v.z+iv.z, v.w+iv.w);
            }
        }
    }
}

// -------- K2: local scan per chunk (carry-in = 0), in place over q --------
// EXACT round-1 version (Wt layout, 4 coalesced scalar weight loads, unroll 4).
__global__ void __launch_bounds__(512, 1)
k_local(const float* __restrict__ Wt, float* __restrict__ q, float* __restrict__ lend)
{
    __shared__ __align__(16) float hs[N_][H_];
    const int c = blockIdx.x;
    const int j = threadIdx.x;
    const int t0 = c * L_;

    float acc[N_];
#pragma unroll
    for (int n = 0; n < N_; ++n) {
        acc[n] = q[((size_t)n*T_ + t0)*H_ + j];   // l[t0] = q[t0]
        hs[n][j] = acc[n];
    }
    __syncthreads();

    for (int s = 1; s < L_; ++s) {
        const size_t t = (size_t)t0 + s;
#pragma unroll
        for (int n = 0; n < N_; ++n)
            acc[n] = q[((size_t)n*T_ + t)*H_ + j];
#pragma unroll 4
        for (int k4 = 0; k4 < H_/4; ++k4) {
            const int k = k4 * 4;
            float w0 = Wt[(k+0)*H_ + j];
            float w1 = Wt[(k+1)*H_ + j];
            float w2 = Wt[(k+2)*H_ + j];
            float w3 = Wt[(k+3)*H_ + j];
#pragma unroll
            for (int n = 0; n < N_; ++n) {
                float4 h = *(const float4*)&hs[n][k];
                acc[n] = fmaf(h.x, w0, acc[n]);
                acc[n] = fmaf(h.y, w1, acc[n]);
                acc[n] = fmaf(h.z, w2, acc[n]);
                acc[n] = fmaf(h.w, w3, acc[n]);
            }
        }
        __syncthreads();
#pragma unroll
        for (int n = 0; n < N_; ++n) {
            hs[n][j] = acc[n];
            q[((size_t)n*T_ + t)*H_ + j] = acc[n];
        }
        __syncthreads();
    }
#pragma unroll
    for (int n = 0; n < N_; ++n)
        lend[((size_t)c*N_ + n)*H_ + j] = acc[n];
}

// -------- K4: boundary scan (persistent, grid barrier) — round-1 version --------
// hb[0] = lend[0];  hb[c] = W^L @ hb[c-1] + lend[c];  ML = (W^L)^T row-major.
__global__ void __launch_bounds__(128, 1)
k_bscan(const float* __restrict__ ML, const float* __restrict__ lend, float* __restrict__ hb)
{
    const int b   = blockIdx.x;
    const int tid = threadIdx.x;
    const unsigned total = gridDim.x;          // 64
    const int n = tid >> 3;                    // 0..15
    const int j = b * 8 + (tid & 7);           // 0..511

    {
        int idx = b * 128 + tid;               // 64*128 = 8192 = N*H
        __stcg(&hb[idx], lend[idx]);
    }
    grid_barrier_dev(total);

    for (int c = 1; c < C_; ++c) {
        const float4* hp4 = (const float4*)(hb + (size_t)(c-1)*N_*H_ + (size_t)n*H_);
        float a0 = 0.f, a1 = 0.f, a2 = 0.f, a3 = 0.f;
#pragma unroll 4
        for (int k4 = 0; k4 < H_/4; ++k4) {
            float4 h = __ldcg(&hp4[k4]);       // peer-CTA data: L2 path
            const int k = k4 * 4;
            a0 = fmaf(h.x, ML[(size_t)(k+0)*H_ + j], a0);
            a1 = fmaf(h.y, ML[(size_t)(k+1)*H_ + j], a1);
            a2 = fmaf(h.z, ML[(size_t)(k+2)*H_ + j], a2);
            a3 = fmaf(h.w, ML[(size_t)(k+3)*H_ + j], a3);
        }
        float acc = lend[(size_t)c*N_*H_ + (size_t)n*H_ + j] + ((a0 + a1) + (a2 + a3));
        __stcg(&hb[(size_t)c*N_*H_ + (size_t)n*H_ + j], acc);
        grid_barrier_dev(total);
    }
}

// -------- K5: correction pass per chunk — round-1 version --------
__global__ void __launch_bounds__(512, 1)
k_corr(const float* __restrict__ Wt, const float* __restrict__ hb,
       float* __restrict__ out0, float* __restrict__ out1, int dup)
{
    const int c = blockIdx.x;
    const int j = threadIdx.x;

    if (c == 0) {   // chunk 0: local state IS the answer; just mirror to out1
        if (dup) {
            for (int s = 0; s < L_; ++s) {
#pragma unroll
                for (int n = 0; n < N_; ++n) {
                    size_t idx = ((size_t)n*T_ + s)*H_ + j;
                    out1[idx] = out0[idx];
                }
            }
        }
        return;
    }

    __shared__ __align__(16) float ds[N_][H_];
    const int t0 = c * L_;
#pragma unroll
    for (int n = 0; n < N_; ++n)
        ds[n][j] = hb[((size_t)(c-1)*N_ + n)*H_ + j];
    __syncthreads();

    for (int s = 0; s < L_; ++s) {
        const size_t t = (size_t)t0 + s;
        float acc[N_];
#pragma unroll
        for (int n = 0; n < N_; ++n) acc[n] = 0.f;
#pragma unroll 4
        for (int k4 = 0; k4 < H_/4; ++k4) {
            const int k = k4 * 4;
            float w0 = Wt[(k+0)*H_ + j];
            float w1 = Wt[(k+1)*H_ + j];
            float w2 = Wt[(k+2)*H_ + j];
            float w3 = Wt[(k+3)*H_ + j];
#pragma unroll
            for (int n = 0; n < N_; ++n) {
                float4 h = *(const float4*)&ds[n][k];
                acc[n] = fmaf(h.x, w0, acc[n]);
                acc[n] = fmaf(h.y, w1, acc[n]);
                acc[n] = fmaf(h.z, w2, acc[n]);
                acc[n] = fmaf(h.w, w3, acc[n]);
            }
        }
        __syncthreads();
#pragma unroll
        for (int n = 0; n < N_; ++n) {
            ds[n][j] = acc[n];
            size_t idx = ((size_t)n*T_ + t)*H_ + j;
            float v = out0[idx] + acc[n];
            out0[idx] = v;
            if (dup) out1[idx] = v;
        }
        __syncthreads();
    }
}

// ----------------------------------------------------------------------------
extern "C" void kernel_launch(void* const* d_in, const int* in_sizes, int n_in,
                              void* d_out, int out_size)
{
    const float *x = nullptr, *initial = nullptr, *Wi = nullptr, *bi = nullptr, *Whh = nullptr;
    for (int i = 0; i < n_in; ++i) {
        switch (in_sizes[i]) {
            case N_*T_*I_: x       = (const float*)d_in[i]; break;
            case N_*H_:    initial = (const float*)d_in[i]; break;
            case H_*I_:    Wi      = (const float*)d_in[i]; break;
            case H_:       bi      = (const float*)d_in[i]; break;
            case H_*H_:    Whh     = (const float*)d_in[i]; break;
        }
    }
    if (!x       && n_in > 0) x       = (const float*)d_in[0];
    if (!initial && n_in > 1) initial = (const float*)d_in[1];
    if (!Wi      && n_in > 2) Wi      = (const float*)d_in[2];
    if (!bi      && n_in > 3) bi      = (const float*)d_in[3];
    if (!Whh     && n_in > 4) Whh     = (const float*)d_in[4];

    float* out0 = (float*)d_out;
    const size_t NTH = (size_t)N_ * T_ * H_;
    int dup = ((size_t)out_size >= 2 * NTH) ? 1 : 0;
    float* out1 = out0 + NTH;

    float *Wt, *Wit, *P0, *P1, *lend, *hb;
    cudaGetSymbolAddress((void**)&Wt,   g_Wt);
    cudaGetSymbolAddress((void**)&Wit,  g_Wit);
    cudaGetSymbolAddress((void**)&P0,   g_P0);
    cudaGetSymbolAddress((void**)&P1,   g_P1);
    cudaGetSymbolAddress((void**)&lend, g_lend);
    cudaGetSymbolAddress((void**)&hb,   g_hb);

    dim3 gs(H_/64, H_/128);        // squaring grid (8, 4)

    // #1: weight layouts
    k_prep<<<(H_*H_ + 255)/256, 256>>>(Whh, Wi);

    // #2: projection q into out0:  q = x @ Wit  (+ shift/bias/initial epilogue)
    {
        dim3 g(H_/64, (N_*T_)/128);   // (8, 512)
        gemm_k<1><<<g, 256>>>(x, Wit, out0, N_*T_, I_, H_, bi, initial);
    }

    // #3-4: first two squarings of S = Whh^T (row-major chain)
    gemm_k<0><<<gs, 256>>>(Wt, Wt, P0, H_, H_, H_, nullptr, nullptr); // S^2
    gemm_k<0><<<gs, 256>>>(P0, P0, P1, H_, H_, H_, nullptr, nullptr); // S^4

    // #5 (ncu -s 5 -c 1 lands here per r4 offset evidence): local scan
    k_local<<<C_, 512>>>(Wt, out0, lend);

    // #6-8: remaining squarings -> P0 = S^32 = (Whh^32)^T row-major
    gemm_k<0><<<gs, 256>>>(P1, P1, P0, H_, H_, H_, nullptr, nullptr); // S^8
    gemm_k<0><<<gs, 256>>>(P0, P0, P1, H_, H_, H_, nullptr, nullptr); // S^16
    gemm_k<0><<<gs, 256>>>(P1, P1, P0, H_, H_, H_, nullptr, nullptr); // S^32

    // #9: boundary scan (persistent kernel, 64 CTAs, grid barrier)
    k_bscan<<<64, 128>>>(P0, lend, hb);

    // #10: correction + finalize (+ duplicate output)
    k_corr<<<C_, 512>>>(Wt, hb, out0, out1, dup);
}

// round 8
// speedup vs baseline: 1.3464x; 1.3464x over previous
#include <cuda_runtime.h>
#include <cuda_bf16.h>
#include <cstdint>

#define N_  16
#define T_  4096
#define I_  256
#define H_  512
#define C_  128
#define L_  32
#define M_ROWS (C_*N_)

// ---------------- portable warp-MMA helpers (sm_80+ PTX, valid on base sm_103) ----
__device__ __forceinline__ void ldsm4(uint32_t r[4], uint32_t addr) {
    asm volatile("ldmatrix.sync.aligned.m8n8.x4.shared.b16 {%0,%1,%2,%3}, [%4];"
        : "=r"(r[0]), "=r"(r[1]), "=r"(r[2]), "=r"(r[3]) : "r"(addr));
}
__device__ __forceinline__ void mma16816(float c[4], const uint32_t a[4],
                                         uint32_t b0, uint32_t b1) {
    asm volatile("mma.sync.aligned.m16n8k16.row.col.f32.bf16.bf16.f32 "
        "{%0,%1,%2,%3}, {%4,%5,%6,%7}, {%8,%9}, {%0,%1,%2,%3};"
        : "+f"(c[0]), "+f"(c[1]), "+f"(c[2]), "+f"(c[3])
        : "r"(a[0]), "r"(a[1]), "r"(a[2]), "r"(a[3]), "r"(b0), "r"(b1));
}
__device__ __forceinline__ uint32_t smem_u32(const void* p) {
    uint32_t a;
    asm("{ .reg .u64 t; cvta.to.shared.u64 t, %1; cvt.u32.u64 %0, t; }" : "=r"(a) : "l"(p));
    return a;
}
// pack two fp32 -> bf16x2 (lo arg -> low half)
__device__ __forceinline__ uint32_t pkbf2(float lo, float hi) {
    uint32_t r;
    asm("cvt.rn.bf16x2.f32 %0, %1, %2;" : "=r"(r) : "f"(hi), "f"(lo));
    return r;
}
// 16B-granule XOR swizzle: row r, logical 16B-col c
__device__ __forceinline__ int swz(int r, int c) { return (c & ~7) | ((c ^ r) & 7); }

// -------- static device scratch --------
__device__ float g_Wt [H_*H_];
__device__ float g_Wit[I_*H_];
__device__ float g_P0 [H_*H_];
__device__ float g_P1 [H_*H_];
__device__ float g_hb [C_*N_*H_];
__device__ __nv_bfloat16 g_Wh [H_*H_];
__device__ __nv_bfloat16 g_Wl [H_*H_];
__device__ __nv_bfloat16 g_Sh0[M_ROWS*H_];
__device__ __nv_bfloat16 g_Sl0[M_ROWS*H_];
__device__ __nv_bfloat16 g_Sh1[M_ROWS*H_];
__device__ __nv_bfloat16 g_Sl1[M_ROWS*H_];

// monotonic grid-barrier counters (separate pairs per kernel family; graph-replay safe)
__device__ unsigned g_cnt  = 0, g_rel  = 0;   // bscan (total=64)
__device__ unsigned g_scnt = 0, g_srel = 0;   // scan  (total=128)

__device__ __forceinline__ void grid_barrier_on(unsigned* cnt, unsigned* rel, unsigned total)
{
    __syncthreads();
    if (threadIdx.x == 0) {
        __threadfence();
        unsigned my = atomicAdd(cnt, 1u);
        if ((my % total) == total - 1u) atomicAdd(rel, 1u);
        else {
            unsigned need = my / total + 1u;
            while (*((volatile unsigned*)rel) < need) { }
        }
    }
    __syncthreads();
}

// -------- K0: transposes + bf16 splits of Whh --------
__global__ void k_prep(const float* __restrict__ Whh, const float* __restrict__ Wi)
{
    int idx = blockIdx.x * blockDim.x + threadIdx.x;
    if (idx < H_*H_) {
        int j = idx / H_, k = idx % H_;
        float w = Whh[idx];
        g_Wt[k*H_ + j] = w;
        __nv_bfloat16 hi = __float2bfloat16(w);
        g_Wh[idx] = hi;
        g_Wl[idx] = __float2bfloat16(w - __bfloat162float(hi));
    }
    if (idx < H_*I_) {
        int j = idx / I_, i = idx % I_;
        g_Wit[i*H_ + j] = Wi[idx];
    }
}

// -------- FFMA GEMM (proven): C = A[M,K]@B[K,Nn]; MODE1 = proj epilogue --------
template<int MODE>
__global__ void __launch_bounds__(256, 2)
gemm_k(const float* __restrict__ A, const float* __restrict__ B,
       float* __restrict__ Cc, int M, int K, int Nn,
       const float* __restrict__ bias, const float* __restrict__ initial)
{
    __shared__ __align__(16) float As[16][136];
    __shared__ __align__(16) float Bs[16][64];
    const int tid = threadIdx.x;
    const int bm = blockIdx.y * 128, bn = blockIdx.x * 64;
    const int tx = tid & 15, ty = tid >> 4;
    const int arow = tid >> 1, akof = (tid & 1) * 8;
    const int brow = tid >> 4, bcol = (tid & 15) * 4;

    float acc[8][4];
#pragma unroll
    for (int i = 0; i < 8; ++i)
#pragma unroll
        for (int jj = 0; jj < 4; ++jj) acc[i][jj] = 0.f;

    for (int kt = 0; kt < K; kt += 16) {
        const float* Ab = A + (size_t)(bm + arow) * K + kt + akof;
        float4 a0 = *(const float4*)&Ab[0];
        float4 a1 = *(const float4*)&Ab[4];
        As[akof+0][arow] = a0.x; As[akof+1][arow] = a0.y;
        As[akof+2][arow] = a0.z; As[akof+3][arow] = a0.w;
        As[akof+4][arow] = a1.x; As[akof+5][arow] = a1.y;
        As[akof+6][arow] = a1.z; As[akof+7][arow] = a1.w;
        *(float4*)&Bs[brow][bcol] = *(const float4*)&B[(size_t)(kt + brow) * Nn + bn + bcol];
        __syncthreads();
#pragma unroll
        for (int k = 0; k < 16; ++k) {
            float4 av0 = *(const float4*)&As[k][ty*8];
            float4 av1 = *(const float4*)&As[k][ty*8 + 4];
            float4 bv  = *(const float4*)&Bs[k][tx*4];
            float am[8] = {av0.x,av0.y,av0.z,av0.w, av1.x,av1.y,av1.z,av1.w};
            float bb[4] = {bv.x,bv.y,bv.z,bv.w};
#pragma unroll
            for (int i = 0; i < 8; ++i)
#pragma unroll
                for (int jj = 0; jj < 4; ++jj)
                    acc[i][jj] = fmaf(am[i], bb[jj], acc[i][jj]);
        }
        __syncthreads();
    }
    if (MODE == 0) {
#pragma unroll
        for (int i = 0; i < 8; ++i) {
            int m = bm + ty*8 + i;
            *(float4*)&Cc[(size_t)m * Nn + bn + tx*4]
                = make_float4(acc[i][0], acc[i][1], acc[i][2], acc[i][3]);
        }
    } else {
        float4 bv = *(const float4*)&bias[bn + tx*4];
#pragma unroll
        for (int i = 0; i < 8; ++i) {
            int r = bm + ty*8 + i;
            int s = r & (T_ - 1);
            int n = r >> 12;
            float4 v = make_float4(acc[i][0]+bv.x, acc[i][1]+bv.y, acc[i][2]+bv.z, acc[i][3]+bv.w);
            if (s < T_ - 1)
                *(float4*)&Cc[((size_t)n*T_ + s + 1)*H_ + bn + tx*4] = v;
            if (s == 0) {
                float4 iv = *(const float4*)&initial[(size_t)n*H_ + bn + tx*4];
                *(float4*)&Cc[((size_t)n*T_)*H_ + bn + tx*4]
                    = make_float4(v.x+iv.x, v.y+iv.y, v.z+iv.z, v.w+iv.w);
            }
        }
    }
}

// ---------------------------------------------------------------------------
// k_scan: persistent batched scan on warp tensor cores (mma.sync bf16, 3-term split).
// 128 CTAs: bx = blockIdx.x & 15 (M tile of 128 state rows), by = >>4 (64 features).
// local (is_corr=0): init S=q[t0]; s=1..31: v = W*S + q[t]; out0[t]=v; S=v.
// corr  (is_corr=1): init S=hb[c-1] (0 @ c=0); s=0..31: D=W*S; h=l+D; out0=out1=h; S=D.
// State splits ping-pong via global bf16 buffers (stcg/ldcg across grid barrier).
// SMEM: Bh 64KB | Bl 64KB | Ah 16KB | Al 16KB = 160KB dynamic.
// ---------------------------------------------------------------------------
#define BH_OFF 0
#define BL_OFF 65536
#define AH_OFF 131072
#define AL_OFF 147456
#define SM_SCAN 163840

__global__ void __launch_bounds__(256, 1)
k_scan(float* __restrict__ out0, float* __restrict__ out1, int is_corr, int dup)
{
    extern __shared__ __align__(128) char smem[];
    const uint32_t sb = smem_u32(smem);
    const int tid = threadIdx.x;
    const int wid = tid >> 5, lane = tid & 31;
    const int bx = blockIdx.x & 15;
    const int by = blockIdx.x >> 4;

    __nv_bfloat16* SH[2] = {g_Sh0, g_Sh1};
    __nv_bfloat16* SL[2] = {g_Sl0, g_Sl1};

    // ---- stage B (Whh bf16 splits, rows = features of this slice) once ----
    for (int idx = tid; idx < 64*64; idx += 256) {
        int r = idx >> 6, c = idx & 63;
        int dst = r*1024 + swz(r, c)*16;
        *(uint4*)(smem + BH_OFF + dst) = *((const uint4*)(g_Wh + (size_t)(by*64 + r)*H_) + c);
        *(uint4*)(smem + BL_OFF + dst) = *((const uint4*)(g_Wl + (size_t)(by*64 + r)*H_) + c);
    }

    // ---- init state splits for this CTA's (rows, cols) block ----
    {
        const int ar = tid >> 1;
        const int m  = bx*128 + ar;
        const int colbase = by*64 + (tid & 1)*32;
        const int cch = m >> 4, n = m & 15;
        const int ib = is_corr ? 1 : 0;
#pragma unroll
        for (int p = 0; p < 16; ++p) {
            int colg = colbase + 2*p;
            float2 v;
            if (!is_corr) v = *(const float2*)&out0[((size_t)n*T_ + cch*L_)*H_ + colg];
            else if (cch) v = *(const float2*)&g_hb[((size_t)(cch-1)*N_ + n)*H_ + colg];
            else          v = make_float2(0.f, 0.f);
            uint32_t hi = pkbf2(v.x, v.y);
            float ux = __uint_as_float(hi << 16);
            float uy = __uint_as_float(hi & 0xffff0000u);
            uint32_t lo = pkbf2(v.x - ux, v.y - uy);
            size_t so = (size_t)m*H_ + colg;
            __stcg((unsigned int*)(SH[ib] + so), hi);
            __stcg((unsigned int*)(SL[ib] + so), lo);
        }
    }
    grid_barrier_on(&g_scnt, &g_srel, 128);

    // per-lane fragment address components
    const int lr = lane & 15, lh = lane >> 4;
    const int rA0 = (wid & 3)*32 + lr;          // mi=0 rows; mi=1 adds 16
    const int rB0 = (wid >> 2)*32 + lr;         // nb=0 rows; nb=1 adds 16
    const int s_begin = is_corr ? 0 : 1;

    for (int s = s_begin; s < L_; ++s) {
        const __nv_bfloat16* ShIn = SH[(s-1) & 1];
        const __nv_bfloat16* SlIn = SL[(s-1) & 1];
        __nv_bfloat16* ShOut = SH[s & 1];
        __nv_bfloat16* SlOut = SL[s & 1];

        float acc[2][4][4];
#pragma unroll
        for (int a = 0; a < 2; ++a)
#pragma unroll
            for (int b = 0; b < 4; ++b)
#pragma unroll
                for (int cc = 0; cc < 4; ++cc) acc[a][b][cc] = 0.f;

        for (int kc = 0; kc < 8; ++kc) {
            __syncthreads();   // protect A smem from previous chunk's consumers
            // stage A chunk: 128 rows x 64 k from state splits (cross-CTA -> ldcg)
            {
                const int ar = tid >> 1;
                const int c0 = (tid & 1) * 4;
                const int m  = bx*128 + ar;
                const uint4* srcH = (const uint4*)(ShIn + (size_t)m*H_) + kc*8;
                const uint4* srcL = (const uint4*)(SlIn + (size_t)m*H_) + kc*8;
#pragma unroll
                for (int i = 0; i < 4; ++i) {
                    int c = c0 + i;
                    int dst = ar*128 + swz(ar, c)*16;
                    *(uint4*)(smem + AH_OFF + dst) = __ldcg(srcH + c);
                    *(uint4*)(smem + AL_OFF + dst) = __ldcg(srcL + c);
                }
            }
            __syncthreads();

            // compute 4 k16 sub-steps
#pragma unroll
            for (int kk = 0; kk < 4; ++kk) {
                uint32_t ah[2][4], al[2][4], bh[2][4], bl[2][4];
#pragma unroll
                for (int mi = 0; mi < 2; ++mi) {
                    int r = rA0 + mi*16;
                    int off = r*128 + swz(r, kk*2 + lh)*16;
                    ldsm4(ah[mi], sb + AH_OFF + off);
                    ldsm4(al[mi], sb + AL_OFF + off);
                }
#pragma unroll
                for (int nb = 0; nb < 2; ++nb) {
                    int r = rB0 + nb*16;
                    int off = r*1024 + swz(r, (kc*4 + kk)*2 + lh)*16;
                    ldsm4(bh[nb], sb + BH_OFF + off);
                    ldsm4(bl[nb], sb + BL_OFF + off);
                }
#pragma unroll
                for (int mi = 0; mi < 2; ++mi)
#pragma unroll
                    for (int nb = 0; nb < 2; ++nb) {
                        mma16816(acc[mi][nb*2+0], ah[mi], bh[nb][0], bh[nb][2]);
                        mma16816(acc[mi][nb*2+1], ah[mi], bh[nb][1], bh[nb][3]);
                        mma16816(acc[mi][nb*2+0], ah[mi], bl[nb][0], bl[nb][2]);
                        mma16816(acc[mi][nb*2+1], ah[mi], bl[nb][1], bl[nb][3]);
                        mma16816(acc[mi][nb*2+0], al[mi], bh[nb][0], bh[nb][2]);
                        mma16816(acc[mi][nb*2+1], al[mi], bh[nb][1], bh[nb][3]);
                    }
            }
        }

        // ---- epilogue ----
#pragma unroll
        for (int mi = 0; mi < 2; ++mi) {
            int mrow = bx*128 + (wid & 3)*32 + mi*16 + (lane >> 2);
#pragma unroll
            for (int nj = 0; nj < 4; ++nj) {
                int colg = by*64 + (wid >> 2)*32 + nj*8 + 2*(lane & 3);
#pragma unroll
                for (int half = 0; half < 2; ++half) {
                    int m = mrow + half*8;
                    float dx = acc[mi][nj][half*2+0];
                    float dy = acc[mi][nj][half*2+1];
                    int cch = m >> 4, n = m & 15;
                    int t = cch*L_ + s;
                    size_t o = ((size_t)n*T_ + t)*H_ + colg;
                    float2 add = *(const float2*)&out0[o];
                    float2 hv = make_float2(dx + add.x, dy + add.y);
                    *(float2*)&out0[o] = hv;
                    float sx, sy;
                    if (is_corr) {
                        if (dup) *(float2*)&out1[o] = hv;
                        sx = dx; sy = dy;            // carry pure D
                    } else {
                        sx = hv.x; sy = hv.y;        // carry state
                    }
                    uint32_t hi = pkbf2(sx, sy);
                    float ux = __uint_as_float(hi << 16);
                    float uy = __uint_as_float(hi & 0xffff0000u);
                    uint32_t lo = pkbf2(sx - ux, sy - uy);
                    size_t so = (size_t)m*H_ + colg;
                    __stcg((unsigned int*)(ShOut + so), hi);
                    __stcg((unsigned int*)(SlOut + so), lo);
                }
            }
        }
        grid_barrier_on(&g_scnt, &g_srel, 128);
    }
}

// -------- boundary scan (persistent FFMA, proven); lend read from out0[t=c*32+31] --------
__global__ void __launch_bounds__(128, 1)
k_bscan(const float* __restrict__ ML, const float* __restrict__ out0, float* __restrict__ hb)
{
    const int b = blockIdx.x, tid = threadIdx.x;
    const unsigned total = gridDim.x;          // 64
    const int n = tid >> 3, j = b * 8 + (tid & 7);

    {
        int idx = b * 128 + tid;               // over N*H
        int nn = idx >> 9, jj = idx & 511;
        __stcg(&hb[idx], out0[((size_t)nn*T_ + (L_-1))*H_ + jj]);
    }
    grid_barrier_on(&g_cnt, &g_rel, total);

    for (int c = 1; c < C_; ++c) {
        const float4* hp4 = (const float4*)(hb + (size_t)(c-1)*N_*H_ + (size_t)n*H_);
        float a0 = 0.f, a1 = 0.f, a2 = 0.f, a3 = 0.f;
#pragma unroll 4
        for (int k4 = 0; k4 < H_/4; ++k4) {
            float4 h = __ldcg(&hp4[k4]);
            const int k = k4 * 4;
            a0 = fmaf(h.x, ML[(size_t)(k+0)*H_ + j], a0);
            a1 = fmaf(h.y, ML[(size_t)(k+1)*H_ + j], a1);
            a2 = fmaf(h.z, ML[(size_t)(k+2)*H_ + j], a2);
            a3 = fmaf(h.w, ML[(size_t)(k+3)*H_ + j], a3);
        }
        float lend = out0[((size_t)n*T_ + c*L_ + (L_-1))*H_ + j];
        float acc = lend + ((a0 + a1) + (a2 + a3));
        __stcg(&hb[(size_t)c*N_*H_ + (size_t)n*H_ + j], acc);
        grid_barrier_on(&g_cnt, &g_rel, total);
    }
}

// ----------------------------------------------------------------------------
extern "C" void kernel_launch(void* const* d_in, const int* in_sizes, int n_in,
                              void* d_out, int out_size)
{
    const float *x = nullptr, *initial = nullptr, *Wi = nullptr, *bi = nullptr, *Whh = nullptr;
    for (int i = 0; i < n_in; ++i) {
        switch (in_sizes[i]) {
            case N_*T_*I_: x       = (const float*)d_in[i]; break;
            case N_*H_:    initial = (const float*)d_in[i]; break;
            case H_*I_:    Wi      = (const float*)d_in[i]; break;
            case H_:       bi      = (const float*)d_in[i]; break;
            case H_*H_:    Whh     = (const float*)d_in[i]; break;
        }
    }
    if (!x       && n_in > 0) x       = (const float*)d_in[0];
    if (!initial && n_in > 1) initial = (const float*)d_in[1];
    if (!Wi      && n_in > 2) Wi      = (const float*)d_in[2];
    if (!bi      && n_in > 3) bi      = (const float*)d_in[3];
    if (!Whh     && n_in > 4) Whh     = (const float*)d_in[4];

    float* out0 = (float*)d_out;
    const size_t NTH = (size_t)N_ * T_ * H_;
    int dup = ((size_t)out_size >= 2 * NTH) ? 1 : 0;
    float* out1 = out0 + NTH;

    float *Wt, *Wit, *P0, *P1, *hb;
    cudaGetSymbolAddress((void**)&Wt,  g_Wt);
    cudaGetSymbolAddress((void**)&Wit, g_Wit);
    cudaGetSymbolAddress((void**)&P0,  g_P0);
    cudaGetSymbolAddress((void**)&P1,  g_P1);
    cudaGetSymbolAddress((void**)&hb,  g_hb);

    cudaFuncSetAttribute(k_scan, cudaFuncAttributeMaxDynamicSharedMemorySize, SM_SCAN);

    dim3 gs(H_/64, H_/128);

    // #1: weight layouts + bf16 splits
    k_prep<<<(H_*H_ + 255)/256, 256>>>(Whh, Wi);

    // #2: projection q into out0 (q[t]=proj[t-1]+bias, q[0]+=initial)
    {
        dim3 g(H_/64, (N_*T_)/128);
        gemm_k<1><<<g, 256>>>(x, Wit, out0, N_*T_, I_, H_, bi, initial);
    }

    // #3-7: S^32 chain on S = Whh^T -> P0 = (Whh^32)^T row-major (bscan ML)
    gemm_k<0><<<gs, 256>>>(Wt, Wt, P0, H_, H_, H_, nullptr, nullptr);
    gemm_k<0><<<gs, 256>>>(P0, P0, P1, H_, H_, H_, nullptr, nullptr);
    gemm_k<0><<<gs, 256>>>(P1, P1, P0, H_, H_, H_, nullptr, nullptr);
    gemm_k<0><<<gs, 256>>>(P0, P0, P1, H_, H_, H_, nullptr, nullptr);
    gemm_k<0><<<gs, 256>>>(P1, P1, P0, H_, H_, H_, nullptr, nullptr);

    // #8: local scan (persistent, tensor cores)
    k_scan<<<128, 256, SM_SCAN>>>(out0, out1, 0, dup);

    // #9: boundary scan
    k_bscan<<<64, 128>>>(P0, out0, hb);

    // #10: correction scan (persistent, tensor cores)
    k_scan<<<128, 256, SM_SCAN>>>(out0, out1, 1, dup);
}